// round 5
// baseline (speedup 1.0000x reference)
#include <cuda_runtime.h>

#define Hh 720
#define Ww 1440
#define BW 10
#define RSTRIP 40          // output rows per strip (720 = 18 * 40)

__device__ __forceinline__ float4 f4add(const float4 a, const float4 b) {
    return make_float4(a.x + b.x, a.y + b.y, a.z + b.z, a.w + b.w);
}
__device__ __forceinline__ float4 f4sub(const float4 a, const float4 b) {
    return make_float4(a.x - b.x, a.y - b.y, a.z - b.z, a.w - b.w);
}
__device__ __forceinline__ float4 f4scale(const float4 a, const float s) {
    return make_float4(a.x * s, a.y * s, a.z * s, a.w * s);
}
__device__ __forceinline__ void stcs4(float* p, const float4 v) {
    asm volatile("st.global.cs.v4.f32 [%0], {%1,%2,%3,%4};"
                 :: "l"(p), "f"(v.x), "f"(v.y), "f"(v.z), "f"(v.w) : "memory");
}

// Horizontal 5-sums for this lane's 4 cols, neighbors via warp shuffle.
__device__ __forceinline__ float4 hshuf(const float4 B, const float2 hl,
                                        const float2 hr, const int lane)
{
    float Lx = __shfl_up_sync(0xffffffffu, B.z, 1);
    float Ly = __shfl_up_sync(0xffffffffu, B.w, 1);
    float Rx = __shfl_down_sync(0xffffffffu, B.x, 1);
    float Ry = __shfl_down_sync(0xffffffffu, B.y, 1);
    if (lane == 0)  { Lx = hl.x; Ly = hl.y; }
    if (lane == 31) { Rx = hr.x; Ry = hr.y; }
    float4 h;
    h.x = ((Lx + Ly) + (B.x + B.y)) + B.z;
    h.y = h.x - Lx + B.w;
    h.z = h.y - Ly + Rx;
    h.w = h.z - B.x + Ry;
    return h;
}

__global__ __launch_bounds__(128, 10)
void seg_smooth(const float* __restrict__ x, float* __restrict__ out)
{
    const int tid   = threadIdx.x;
    const int gi0   = blockIdx.y * RSTRIP;
    const int plane = blockIdx.z;
    const float* __restrict__ xp = x   + (size_t)plane * (Hh * Ww);
    float* __restrict__       op = out + (size_t)plane * (Hh * Ww);

    if (blockIdx.x < 3) {
        // ========== pure columns: shuffle exchange + rolling ring ==========
        const int g    = blockIdx.x * 128 + tid;      // 0..383
        const int lane = tid & 31;
        const int cb   = 4 * g;                       // own cols cb..cb+3
        const bool colok    = (g <= 359);
        const bool do_store = (g >= 3 && g <= 356);
        const bool lhok     = (lane == 0)  && (g >= 1);
        const bool rhok     = (lane == 31) && (g <= 358);
        const float* bp = xp + cb;                    // row offset added per use

        // ---- warmup: h for rows gi0-2 .. gi0+1 ----
        float4 h[5];
        #pragma unroll
        for (int k = 0; k < 4; ++k) {
            const int r = gi0 - 2 + k;
            const bool rok = ((unsigned)r < (unsigned)Hh);
            const size_t ro = (size_t)r * Ww;
            float4 B  = (rok && colok) ? *(const float4*)(bp + ro)
                                       : make_float4(0.f, 0.f, 0.f, 0.f);
            float2 hl = (rok && lhok)  ? *(const float2*)(bp + ro - 2)
                                       : make_float2(0.f, 0.f);
            float2 hr = (rok && rhok)  ? *(const float2*)(bp + ro + 4)
                                       : make_float2(0.f, 0.f);
            h[k] = hshuf(B, hl, hr, lane);
        }
        float4 acc = f4add(f4add(h[0], h[1]), f4add(h[2], h[3]));

        // ---- 2-deep prefetch of raw rows gi0+2, gi0+3 ----
        float4 Bp[2];
        float2 Lp[2], Rp[2];
        #pragma unroll
        for (int s = 0; s < 2; ++s) {
            const int r = gi0 + 2 + s;
            const bool rok = ((unsigned)r < (unsigned)Hh);
            const size_t ro = (size_t)r * Ww;
            Bp[s] = (rok && colok) ? *(const float4*)(bp + ro)
                                   : make_float4(0.f, 0.f, 0.f, 0.f);
            Lp[s] = (rok && lhok)  ? *(const float2*)(bp + ro - 2)
                                   : make_float2(0.f, 0.f);
            Rp[s] = (rok && rhok)  ? *(const float2*)(bp + ro + 4)
                                   : make_float2(0.f, 0.f);
        }

        #pragma unroll 1
        for (int a = 0; a < RSTRIP / 10; ++a) {
            #pragma unroll
            for (int b = 0; b < 10; ++b) {
                const int i  = gi0 + a * 10 + b;
                const int s  = b & 1;
                const int rb = b % 5;

                const float4 hn = hshuf(Bp[s], Lp[s], Rp[s], lane);

                // prefetch row i+4 into slot s
                {
                    const int r = i + 4;
                    const bool rok = ((unsigned)r < (unsigned)Hh);
                    const size_t ro = (size_t)r * Ww;
                    Bp[s] = (rok && colok) ? *(const float4*)(bp + ro)
                                           : make_float4(0.f, 0.f, 0.f, 0.f);
                    Lp[s] = (rok && lhok)  ? *(const float2*)(bp + ro - 2)
                                           : make_float2(0.f, 0.f);
                    Rp[s] = (rok && rhok)  ? *(const float2*)(bp + ro + 4)
                                           : make_float2(0.f, 0.f);
                }

                h[(rb + 4) % 5] = hn;
                const float4 S = f4add(acc, hn);

                float4 o;
                if (i >= BW + 2 && i < Hh - BW - 2) {
                    o = f4scale(S, 0.04f);
                } else {
                    float4 NB = make_float4(0.f, 0.f, 0.f, 0.f);
                    #pragma unroll
                    for (int k = 0; k < 5; ++k) {
                        const int rk = i - 2 + k;     // OOB rows: h == 0
                        if (rk < BW || rk >= Hh - BW)
                            NB = f4add(NB, h[(rb + k) % 5]);
                    }
                    const int r0 = max(i - 2, 0), r1 = min(i + 2, Hh - 1);
                    const int nrows = r1 - r0 + 1;
                    const int nbr = max(0, min(r1, BW - 1) - r0 + 1)
                                  + max(0, r1 - max(r0, Hh - BW) + 1);
                    if (i < BW || i >= Hh - BW)
                        o = f4scale(NB, 1.0f / (float)(5 * nbr));
                    else
                        o = f4scale(f4sub(S, NB), 1.0f / (float)(5 * (nrows - nbr)));
                }
                if (do_store)
                    stcs4(op + (size_t)i * Ww + cb, o);
                acc = f4sub(S, h[rb]);                // drop row i-2
            }
        }
    } else {
        // ========== frame columns 0..11 and 1428..1439 (naive) ==========
        for (int idx = tid; idx < 6 * RSTRIP; idx += 128) {
            const int q  = idx % 6;
            const int i  = gi0 + idx / 6;
            const int gq = (q < 3) ? q : (q + 354);   // {0,1,2,357,358,359}
            const int cb = 4 * gq - 4;
            const bool Aok = (cb >= 0);
            const bool Cok = (cb + 11 < Ww);

            float m[8];
            #pragma unroll
            for (int c = 0; c < 8; ++c) {
                const int col = cb + 2 + c;
                m[c] = (col < BW || col >= Ww - BW) ? 1.0f : 0.0f;
            }

            float4 S  = make_float4(0.f, 0.f, 0.f, 0.f);
            float4 NB = make_float4(0.f, 0.f, 0.f, 0.f);
            #pragma unroll
            for (int k = 0; k < 5; ++k) {
                const int r = i - 2 + k;
                if ((unsigned)r < (unsigned)Hh) {
                    const float* rowp = xp + (size_t)r * Ww;
                    const float4 A = Aok ? *(const float4*)(rowp + cb)
                                         : make_float4(0.f, 0.f, 0.f, 0.f);
                    const float4 B = *(const float4*)(rowp + cb + 4);
                    const float4 C = Cok ? *(const float4*)(rowp + cb + 8)
                                         : make_float4(0.f, 0.f, 0.f, 0.f);
                    float4 h;
                    h.x = ((A.z + A.w) + (B.x + B.y)) + B.z;
                    h.y = h.x - A.z + B.w;
                    h.z = h.y - A.w + C.x;
                    h.w = h.z - B.x + C.y;
                    S = f4add(S, h);
                    if (r < BW || r >= Hh - BW) {
                        NB = f4add(NB, h);
                    } else {
                        const float w0 = A.z * m[0], w1 = A.w * m[1];
                        const float w2 = B.x * m[2], w3 = B.y * m[3];
                        const float w4 = B.z * m[4], w5 = B.w * m[5];
                        const float w6 = C.x * m[6], w7 = C.y * m[7];
                        float4 hb;
                        hb.x = ((w0 + w1) + (w2 + w3)) + w4;
                        hb.y = hb.x - w0 + w5;
                        hb.z = hb.y - w1 + w6;
                        hb.w = hb.z - w2 + w7;
                        NB = f4add(NB, hb);
                    }
                }
            }
            const int r0 = max(i - 2, 0), r1 = min(i + 2, Hh - 1);
            const int nrows = r1 - r0 + 1;
            const int nbr = max(0, min(r1, BW - 1) - r0 + 1)
                          + max(0, r1 - max(r0, Hh - BW) + 1);
            const bool rowBi = (i < BW || i >= Hh - BW);
            const float sv[4]  = {S.x, S.y, S.z, S.w};
            const float nbv[4] = {NB.x, NB.y, NB.z, NB.w};
            float ov[4];
            #pragma unroll
            for (int c = 0; c < 4; ++c) {
                const int j  = cb + 4 + c;
                const int c0 = max(j - 2, 0), c1 = min(j + 2, Ww - 1);
                const int ncols = c1 - c0 + 1;
                const int nbc = max(0, min(c1, BW - 1) - c0 + 1)
                              + max(0, c1 - max(c0, Ww - BW) + 1);
                const int  cntB = nbr * ncols + (nrows - nbr) * nbc;
                const bool mb   = rowBi || (j < BW || j >= Ww - BW);
                const float num = mb ? nbv[c] : (sv[c] - nbv[c]);
                const int   cnt = mb ? cntB : (nrows * ncols - cntB);
                ov[c] = num / (float)cnt;
            }
            stcs4(op + (size_t)i * Ww + (cb + 4),
                  make_float4(ov[0], ov[1], ov[2], ov[3]));
        }
    }
}

extern "C" void kernel_launch(void* const* d_in, const int* in_sizes, int n_in,
                              void* d_out, int out_size)
{
    const float* x = (const float*)d_in[0];
    float* out = (float*)d_out;
    const int planes = out_size / (Hh * Ww);     // 64
    dim3 grid(4, Hh / RSTRIP, planes);           // 4 x 18 x 64 = 4608 blocks
    seg_smooth<<<grid, 128>>>(x, out);
}

// round 6
// speedup vs baseline: 1.3110x; 1.3110x over previous
#include <cuda_runtime.h>

#define Hh 720
#define Ww 1440
#define BW 10
#define RSTRIP 40          // output rows per strip (720 = 18 * 40)

__device__ __forceinline__ float4 f4add(const float4 a, const float4 b) {
    return make_float4(a.x + b.x, a.y + b.y, a.z + b.z, a.w + b.w);
}
__device__ __forceinline__ float4 f4sub(const float4 a, const float4 b) {
    return make_float4(a.x - b.x, a.y - b.y, a.z - b.z, a.w - b.w);
}
__device__ __forceinline__ float4 f4scale(const float4 a, const float s) {
    return make_float4(a.x * s, a.y * s, a.z * s, a.w * s);
}
__device__ __forceinline__ void stcs4(float* p, const float4 v) {
    asm volatile("st.global.cs.v4.f32 [%0], {%1,%2,%3,%4};"
                 :: "l"(p), "f"(v.x), "f"(v.y), "f"(v.z), "f"(v.w) : "memory");
}

// Load 3 aligned float4 covering cols cb..cb+11 of row r (zero-fill OOB rows).
__device__ __forceinline__ void loadraw(const float* __restrict__ xp, int r, int cb,
                                        float4& A, float4& B, float4& C)
{
    if ((unsigned)r < (unsigned)Hh) {
        const float4* p = reinterpret_cast<const float4*>(xp + (size_t)r * Ww + cb);
        A = p[0]; B = p[1]; C = p[2];
    } else {
        A = B = C = make_float4(0.f, 0.f, 0.f, 0.f);
    }
}

__device__ __forceinline__ float4 hfrom(const float4 A, const float4 B, const float4 C)
{
    float4 h;
    h.x = ((A.z + A.w) + (B.x + B.y)) + B.z;
    h.y = h.x - A.z + B.w;
    h.z = h.y - A.w + C.x;
    h.w = h.z - B.x + C.y;
    return h;
}

__global__ __launch_bounds__(128, 6)
void seg_smooth(const float* __restrict__ x, float* __restrict__ out)
{
    const int tid   = threadIdx.x;
    const int gi0   = blockIdx.y * RSTRIP;
    const int plane = blockIdx.z;
    const float* __restrict__ xp = x   + (size_t)plane * (Hh * Ww);
    float* __restrict__       op = out + (size_t)plane * (Hh * Ww);

    if (blockIdx.x < 3) {
        // ========= pure columns 12..1427: rolling ring, 2-row prefetch ======
        const int g = blockIdx.x * 128 + tid;
        if (g < 3 || g > 356) return;
        const int cb = 4 * g - 4;

        float4 h[5];
        {
            float4 A, B, C;
            loadraw(xp, gi0 - 2, cb, A, B, C); h[0] = hfrom(A, B, C);
            loadraw(xp, gi0 - 1, cb, A, B, C); h[1] = hfrom(A, B, C);
            loadraw(xp, gi0    , cb, A, B, C); h[2] = hfrom(A, B, C);
            loadraw(xp, gi0 + 1, cb, A, B, C); h[3] = hfrom(A, B, C);
        }
        float4 acc = f4add(f4add(h[0], h[1]), f4add(h[2], h[3]));

        // 2-deep raw-row prefetch ring: rows gi0+2 (slot 0), gi0+3 (slot 1)
        float4 A[2], B[2], C[2];
        loadraw(xp, gi0 + 2, cb, A[0], B[0], C[0]);
        loadraw(xp, gi0 + 3, cb, A[1], B[1], C[1]);

        #pragma unroll 1
        for (int a = 0; a < RSTRIP / 10; ++a) {
            #pragma unroll
            for (int b = 0; b < 10; ++b) {
                const int i  = gi0 + a * 10 + b;
                const int s  = b & 1;
                const int rb = b % 5;

                const float4 hn = hfrom(A[s], B[s], C[s]);   // h of row i+2
                loadraw(xp, i + 4, cb, A[s], B[s], C[s]);    // prefetch i+4

                h[(rb + 4) % 5] = hn;
                const float4 S = f4add(acc, hn);

                float4 o;
                if (i >= BW + 2 && i < Hh - BW - 2) {
                    o = f4scale(S, 0.04f);
                } else {
                    float4 NB = make_float4(0.f, 0.f, 0.f, 0.f);
                    #pragma unroll
                    for (int k = 0; k < 5; ++k) {
                        const int rk = i - 2 + k;            // OOB rows: h == 0
                        if (rk < BW || rk >= Hh - BW)
                            NB = f4add(NB, h[(rb + k) % 5]);
                    }
                    const int r0 = max(i - 2, 0), r1 = min(i + 2, Hh - 1);
                    const int nrows = r1 - r0 + 1;
                    const int nbr = max(0, min(r1, BW - 1) - r0 + 1)
                                  + max(0, r1 - max(r0, Hh - BW) + 1);
                    if (i < BW || i >= Hh - BW)
                        o = f4scale(NB, 1.0f / (float)(5 * nbr));
                    else
                        o = f4scale(f4sub(S, NB), 1.0f / (float)(5 * (nrows - nbr)));
                }
                stcs4(op + (size_t)i * Ww + (cb + 4), o);
                acc = f4sub(S, h[rb]);                       // drop row i-2
            }
        }
    } else {
        // ========== frame columns 0..11 and 1428..1439 (naive) ==========
        for (int idx = tid; idx < 6 * RSTRIP; idx += 128) {
            const int q  = idx % 6;
            const int i  = gi0 + idx / 6;
            const int gq = (q < 3) ? q : (q + 354);          // {0,1,2,357,358,359}
            const int cb = 4 * gq - 4;
            const bool Aok = (cb >= 0);
            const bool Cok = (cb + 11 < Ww);

            float m[8];
            #pragma unroll
            for (int c = 0; c < 8; ++c) {
                const int col = cb + 2 + c;
                m[c] = (col < BW || col >= Ww - BW) ? 1.0f : 0.0f;
            }

            float4 S  = make_float4(0.f, 0.f, 0.f, 0.f);
            float4 NB = make_float4(0.f, 0.f, 0.f, 0.f);
            #pragma unroll
            for (int k = 0; k < 5; ++k) {
                const int r = i - 2 + k;
                if ((unsigned)r < (unsigned)Hh) {
                    const float* rowp = xp + (size_t)r * Ww;
                    const float4 Af = Aok ? *(const float4*)(rowp + cb)
                                          : make_float4(0.f, 0.f, 0.f, 0.f);
                    const float4 Bf = *(const float4*)(rowp + cb + 4);
                    const float4 Cf = Cok ? *(const float4*)(rowp + cb + 8)
                                          : make_float4(0.f, 0.f, 0.f, 0.f);
                    const float4 h = hfrom(Af, Bf, Cf);
                    S = f4add(S, h);
                    if (r < BW || r >= Hh - BW) {
                        NB = f4add(NB, h);
                    } else {
                        const float w0 = Af.z * m[0], w1 = Af.w * m[1];
                        const float w2 = Bf.x * m[2], w3 = Bf.y * m[3];
                        const float w4 = Bf.z * m[4], w5 = Bf.w * m[5];
                        const float w6 = Cf.x * m[6], w7 = Cf.y * m[7];
                        float4 hb;
                        hb.x = ((w0 + w1) + (w2 + w3)) + w4;
                        hb.y = hb.x - w0 + w5;
                        hb.z = hb.y - w1 + w6;
                        hb.w = hb.z - w2 + w7;
                        NB = f4add(NB, hb);
                    }
                }
            }
            const int r0 = max(i - 2, 0), r1 = min(i + 2, Hh - 1);
            const int nrows = r1 - r0 + 1;
            const int nbr = max(0, min(r1, BW - 1) - r0 + 1)
                          + max(0, r1 - max(r0, Hh - BW) + 1);
            const bool rowBi = (i < BW || i >= Hh - BW);
            const float sv[4]  = {S.x, S.y, S.z, S.w};
            const float nbv[4] = {NB.x, NB.y, NB.z, NB.w};
            float ov[4];
            #pragma unroll
            for (int c = 0; c < 4; ++c) {
                const int j  = cb + 4 + c;
                const int c0 = max(j - 2, 0), c1 = min(j + 2, Ww - 1);
                const int ncols = c1 - c0 + 1;
                const int nbc = max(0, min(c1, BW - 1) - c0 + 1)
                              + max(0, c1 - max(c0, Ww - BW) + 1);
                const int  cntB = nbr * ncols + (nrows - nbr) * nbc;
                const bool mb   = rowBi || (j < BW || j >= Ww - BW);
                const float num = mb ? nbv[c] : (sv[c] - nbv[c]);
                const int   cnt = mb ? cntB : (nrows * ncols - cntB);
                ov[c] = num / (float)cnt;
            }
            stcs4(op + (size_t)i * Ww + (cb + 4),
                  make_float4(ov[0], ov[1], ov[2], ov[3]));
        }
    }
}

extern "C" void kernel_launch(void* const* d_in, const int* in_sizes, int n_in,
                              void* d_out, int out_size)
{
    const float* x = (const float*)d_in[0];
    float* out = (float*)d_out;
    const int planes = out_size / (Hh * Ww);     // 64
    dim3 grid(4, Hh / RSTRIP, planes);           // 4 x 18 x 64 = 4608 blocks
    seg_smooth<<<grid, 128>>>(x, out);
}

// round 7
// speedup vs baseline: 1.3666x; 1.0424x over previous
#include <cuda_runtime.h>

#define Hh 720
#define Ww 1440
#define BW 10
#define RSTRIP 40          // output rows per strip (720 = 18 * 40)

__device__ __forceinline__ float4 f4add(const float4 a, const float4 b) {
    return make_float4(a.x + b.x, a.y + b.y, a.z + b.z, a.w + b.w);
}
__device__ __forceinline__ float4 f4sub(const float4 a, const float4 b) {
    return make_float4(a.x - b.x, a.y - b.y, a.z - b.z, a.w - b.w);
}
__device__ __forceinline__ float4 f4scale(const float4 a, const float s) {
    return make_float4(a.x * s, a.y * s, a.z * s, a.w * s);
}
__device__ __forceinline__ void stcs4(float* p, const float4 v) {
    asm volatile("st.global.cs.v4.f32 [%0], {%1,%2,%3,%4};"
                 :: "l"(p), "f"(v.x), "f"(v.y), "f"(v.z), "f"(v.w) : "memory");
}

// Load the 8 floats this thread's window needs: cols c0-2..c0+5 for outputs
// at c0..c0+3 (c0 = cb+4). L = {c0-2,c0-1}, B = {c0..c0+3}, R = {c0+4,c0+5}.
__device__ __forceinline__ void loadrow8(const float* __restrict__ xp, int r, int cb,
                                         float2& L, float4& B, float2& R)
{
    if ((unsigned)r < (unsigned)Hh) {
        const float* p = xp + (size_t)r * Ww + cb;
        L = *reinterpret_cast<const float2*>(p + 2);   // 8B-aligned
        B = *reinterpret_cast<const float4*>(p + 4);   // 16B-aligned
        R = *reinterpret_cast<const float2*>(p + 8);   // 16B-aligned
    } else {
        L = make_float2(0.f, 0.f);
        B = make_float4(0.f, 0.f, 0.f, 0.f);
        R = make_float2(0.f, 0.f);
    }
}

__device__ __forceinline__ float4 hfrom8(const float2 L, const float4 B, const float2 R)
{
    float4 h;
    h.x = ((L.x + L.y) + (B.x + B.y)) + B.z;
    h.y = h.x - L.x + B.w;
    h.z = h.y - L.y + R.x;
    h.w = h.z - B.x + R.y;
    return h;
}

__global__ __launch_bounds__(128, 8)
void seg_smooth(const float* __restrict__ x, float* __restrict__ out)
{
    const int tid   = threadIdx.x;
    const int gi0   = blockIdx.y * RSTRIP;
    const int plane = blockIdx.z;
    const float* __restrict__ xp = x   + (size_t)plane * (Hh * Ww);
    float* __restrict__       op = out + (size_t)plane * (Hh * Ww);

    if (blockIdx.x < 3) {
        // ========= pure columns 12..1427: rolling ring, 2-row prefetch ======
        const int g = blockIdx.x * 128 + tid;
        if (g < 3 || g > 356) return;
        const int cb = 4 * g - 4;

        float4 h[5];
        {
            float2 L, R; float4 B;
            loadrow8(xp, gi0 - 2, cb, L, B, R); h[0] = hfrom8(L, B, R);
            loadrow8(xp, gi0 - 1, cb, L, B, R); h[1] = hfrom8(L, B, R);
            loadrow8(xp, gi0    , cb, L, B, R); h[2] = hfrom8(L, B, R);
            loadrow8(xp, gi0 + 1, cb, L, B, R); h[3] = hfrom8(L, B, R);
        }
        float4 acc = f4add(f4add(h[0], h[1]), f4add(h[2], h[3]));

        // 2-deep raw-row prefetch ring
        float2 Lp[2], Rp[2]; float4 Bp[2];
        loadrow8(xp, gi0 + 2, cb, Lp[0], Bp[0], Rp[0]);
        loadrow8(xp, gi0 + 3, cb, Lp[1], Bp[1], Rp[1]);

        float* os = op + (size_t)gi0 * Ww + (cb + 4);

        const bool interior = (gi0 >= BW + 2) && (gi0 + RSTRIP <= Hh - BW - 2);
        if (interior) {
            // -------- lean loop: no masked rows anywhere in this strip ------
            #pragma unroll 1
            for (int a = 0; a < RSTRIP / 10; ++a) {
                #pragma unroll
                for (int b = 0; b < 10; ++b) {
                    const int i  = gi0 + a * 10 + b;
                    const int s  = b & 1;
                    const int rb = b % 5;
                    const float4 hn = hfrom8(Lp[s], Bp[s], Rp[s]);
                    loadrow8(xp, i + 4, cb, Lp[s], Bp[s], Rp[s]);
                    h[(rb + 4) % 5] = hn;
                    const float4 S = f4add(acc, hn);
                    stcs4(os, f4scale(S, 0.04f));
                    os += Ww;
                    acc = f4sub(S, h[rb]);
                }
            }
        } else {
            #pragma unroll 1
            for (int a = 0; a < RSTRIP / 10; ++a) {
                #pragma unroll
                for (int b = 0; b < 10; ++b) {
                    const int i  = gi0 + a * 10 + b;
                    const int s  = b & 1;
                    const int rb = b % 5;
                    const float4 hn = hfrom8(Lp[s], Bp[s], Rp[s]);
                    loadrow8(xp, i + 4, cb, Lp[s], Bp[s], Rp[s]);
                    h[(rb + 4) % 5] = hn;
                    const float4 S = f4add(acc, hn);

                    float4 o;
                    if (i >= BW + 2 && i < Hh - BW - 2) {
                        o = f4scale(S, 0.04f);
                    } else {
                        float4 NB = make_float4(0.f, 0.f, 0.f, 0.f);
                        #pragma unroll
                        for (int k = 0; k < 5; ++k) {
                            const int rk = i - 2 + k;        // OOB rows: h == 0
                            if (rk < BW || rk >= Hh - BW)
                                NB = f4add(NB, h[(rb + k) % 5]);
                        }
                        const int r0 = max(i - 2, 0), r1 = min(i + 2, Hh - 1);
                        const int nrows = r1 - r0 + 1;
                        const int nbr = max(0, min(r1, BW - 1) - r0 + 1)
                                      + max(0, r1 - max(r0, Hh - BW) + 1);
                        if (i < BW || i >= Hh - BW)
                            o = f4scale(NB, 1.0f / (float)(5 * nbr));
                        else
                            o = f4scale(f4sub(S, NB),
                                        1.0f / (float)(5 * (nrows - nbr)));
                    }
                    stcs4(os, o);
                    os += Ww;
                    acc = f4sub(S, h[rb]);
                }
            }
        }
    } else {
        // ========== frame columns 0..11 and 1428..1439 (naive) ==========
        for (int idx = tid; idx < 6 * RSTRIP; idx += 128) {
            const int q  = idx % 6;
            const int i  = gi0 + idx / 6;
            const int gq = (q < 3) ? q : (q + 354);          // {0,1,2,357,358,359}
            const int cb = 4 * gq - 4;
            const bool Aok = (cb >= 0);
            const bool Cok = (cb + 11 < Ww);

            float m[8];
            #pragma unroll
            for (int c = 0; c < 8; ++c) {
                const int col = cb + 2 + c;
                m[c] = (col < BW || col >= Ww - BW) ? 1.0f : 0.0f;
            }

            float4 S  = make_float4(0.f, 0.f, 0.f, 0.f);
            float4 NB = make_float4(0.f, 0.f, 0.f, 0.f);
            #pragma unroll
            for (int k = 0; k < 5; ++k) {
                const int r = i - 2 + k;
                if ((unsigned)r < (unsigned)Hh) {
                    const float* rowp = xp + (size_t)r * Ww;
                    const float4 Af = Aok ? *(const float4*)(rowp + cb)
                                          : make_float4(0.f, 0.f, 0.f, 0.f);
                    const float4 Bf = *(const float4*)(rowp + cb + 4);
                    const float4 Cf = Cok ? *(const float4*)(rowp + cb + 8)
                                          : make_float4(0.f, 0.f, 0.f, 0.f);
                    float4 h;
                    h.x = ((Af.z + Af.w) + (Bf.x + Bf.y)) + Bf.z;
                    h.y = h.x - Af.z + Bf.w;
                    h.z = h.y - Af.w + Cf.x;
                    h.w = h.z - Bf.x + Cf.y;
                    S = f4add(S, h);
                    if (r < BW || r >= Hh - BW) {
                        NB = f4add(NB, h);
                    } else {
                        const float w0 = Af.z * m[0], w1 = Af.w * m[1];
                        const float w2 = Bf.x * m[2], w3 = Bf.y * m[3];
                        const float w4 = Bf.z * m[4], w5 = Bf.w * m[5];
                        const float w6 = Cf.x * m[6], w7 = Cf.y * m[7];
                        float4 hb;
                        hb.x = ((w0 + w1) + (w2 + w3)) + w4;
                        hb.y = hb.x - w0 + w5;
                        hb.z = hb.y - w1 + w6;
                        hb.w = hb.z - w2 + w7;
                        NB = f4add(NB, hb);
                    }
                }
            }
            const int r0 = max(i - 2, 0), r1 = min(i + 2, Hh - 1);
            const int nrows = r1 - r0 + 1;
            const int nbr = max(0, min(r1, BW - 1) - r0 + 1)
                          + max(0, r1 - max(r0, Hh - BW) + 1);
            const bool rowBi = (i < BW || i >= Hh - BW);
            const float sv[4]  = {S.x, S.y, S.z, S.w};
            const float nbv[4] = {NB.x, NB.y, NB.z, NB.w};
            float ov[4];
            #pragma unroll
            for (int c = 0; c < 4; ++c) {
                const int j  = cb + 4 + c;
                const int c0 = max(j - 2, 0), c1 = min(j + 2, Ww - 1);
                const int ncols = c1 - c0 + 1;
                const int nbc = max(0, min(c1, BW - 1) - c0 + 1)
                              + max(0, c1 - max(c0, Ww - BW) + 1);
                const int  cntB = nbr * ncols + (nrows - nbr) * nbc;
                const bool mb   = rowBi || (j < BW || j >= Ww - BW);
                const float num = mb ? nbv[c] : (sv[c] - nbv[c]);
                const int   cnt = mb ? cntB : (nrows * ncols - cntB);
                ov[c] = num / (float)cnt;
            }
            stcs4(op + (size_t)i * Ww + (cb + 4),
                  make_float4(ov[0], ov[1], ov[2], ov[3]));
        }
    }
}

extern "C" void kernel_launch(void* const* d_in, const int* in_sizes, int n_in,
                              void* d_out, int out_size)
{
    const float* x = (const float*)d_in[0];
    float* out = (float*)d_out;
    const int planes = out_size / (Hh * Ww);     // 64
    dim3 grid(4, Hh / RSTRIP, planes);           // 4 x 18 x 64 = 4608 blocks
    seg_smooth<<<grid, 128>>>(x, out);
}

// round 8
// speedup vs baseline: 1.3695x; 1.0021x over previous
#include <cuda_runtime.h>

#define Hh 720
#define Ww 1440
#define BW 10
#define RSTRIP 45          // output rows per strip (720 = 16 * 45), 15 | 45

__device__ __forceinline__ float4 f4add(const float4 a, const float4 b) {
    return make_float4(a.x + b.x, a.y + b.y, a.z + b.z, a.w + b.w);
}
__device__ __forceinline__ float4 f4sub(const float4 a, const float4 b) {
    return make_float4(a.x - b.x, a.y - b.y, a.z - b.z, a.w - b.w);
}
__device__ __forceinline__ float4 f4scale(const float4 a, const float s) {
    return make_float4(a.x * s, a.y * s, a.z * s, a.w * s);
}
__device__ __forceinline__ void stcs4(float* p, const float4 v) {
    asm volatile("st.global.cs.v4.f32 [%0], {%1,%2,%3,%4};"
                 :: "l"(p), "f"(v.x), "f"(v.y), "f"(v.z), "f"(v.w) : "memory");
}

// Load the 8 floats this thread's window needs: cols c0-2..c0+5 for outputs
// at c0..c0+3 (c0 = cb+4). L = {c0-2,c0-1}, B = {c0..c0+3}, R = {c0+4,c0+5}.
__device__ __forceinline__ void loadrow8(const float* __restrict__ xp, int r, int cb,
                                         float2& L, float4& B, float2& R)
{
    if ((unsigned)r < (unsigned)Hh) {
        const float* p = xp + (size_t)r * Ww + cb;
        L = *reinterpret_cast<const float2*>(p + 2);   // 8B-aligned
        B = *reinterpret_cast<const float4*>(p + 4);   // 16B-aligned
        R = *reinterpret_cast<const float2*>(p + 8);   // 16B-aligned
    } else {
        L = make_float2(0.f, 0.f);
        B = make_float4(0.f, 0.f, 0.f, 0.f);
        R = make_float2(0.f, 0.f);
    }
}

__device__ __forceinline__ float4 hfrom8(const float2 L, const float4 B, const float2 R)
{
    float4 h;
    h.x = ((L.x + L.y) + (B.x + B.y)) + B.z;
    h.y = h.x - L.x + B.w;
    h.z = h.y - L.y + R.x;
    h.w = h.z - B.x + R.y;
    return h;
}

__global__ __launch_bounds__(128, 7)
void seg_smooth(const float* __restrict__ x, float* __restrict__ out)
{
    const int tid   = threadIdx.x;
    const int gi0   = blockIdx.y * RSTRIP;
    const int plane = blockIdx.z;
    const float* __restrict__ xp = x   + (size_t)plane * (Hh * Ww);
    float* __restrict__       op = out + (size_t)plane * (Hh * Ww);

    if (blockIdx.x < 3) {
        // ========= pure columns 12..1427: rolling ring, 3-row prefetch ======
        const int g = blockIdx.x * 128 + tid;
        if (g < 3 || g > 356) return;
        const int cb = 4 * g - 4;

        float4 h[5];
        {
            float2 L, R; float4 B;
            loadrow8(xp, gi0 - 2, cb, L, B, R); h[0] = hfrom8(L, B, R);
            loadrow8(xp, gi0 - 1, cb, L, B, R); h[1] = hfrom8(L, B, R);
            loadrow8(xp, gi0    , cb, L, B, R); h[2] = hfrom8(L, B, R);
            loadrow8(xp, gi0 + 1, cb, L, B, R); h[3] = hfrom8(L, B, R);
        }
        float4 acc = f4add(f4add(h[0], h[1]), f4add(h[2], h[3]));

        // 3-deep raw-row prefetch ring: rows gi0+2, gi0+3, gi0+4
        float2 Lp[3], Rp[3]; float4 Bp[3];
        loadrow8(xp, gi0 + 2, cb, Lp[0], Bp[0], Rp[0]);
        loadrow8(xp, gi0 + 3, cb, Lp[1], Bp[1], Rp[1]);
        loadrow8(xp, gi0 + 4, cb, Lp[2], Bp[2], Rp[2]);

        float* os = op + (size_t)gi0 * Ww + (cb + 4);

        const bool interior = (gi0 >= BW + 2) && (gi0 + RSTRIP <= Hh - BW - 2);
        if (interior) {
            // -------- lean loop: no masked rows anywhere in this strip ------
            #pragma unroll 1
            for (int a = 0; a < RSTRIP / 15; ++a) {
                #pragma unroll
                for (int b = 0; b < 15; ++b) {
                    const int i  = gi0 + a * 15 + b;
                    const int s  = b % 3;
                    const int rb = b % 5;
                    const float4 hn = hfrom8(Lp[s], Bp[s], Rp[s]);
                    loadrow8(xp, i + 5, cb, Lp[s], Bp[s], Rp[s]);
                    h[(rb + 4) % 5] = hn;
                    const float4 S = f4add(acc, hn);
                    stcs4(os, f4scale(S, 0.04f));
                    os += Ww;
                    acc = f4sub(S, h[rb]);
                }
            }
        } else {
            #pragma unroll 1
            for (int a = 0; a < RSTRIP / 15; ++a) {
                #pragma unroll
                for (int b = 0; b < 15; ++b) {
                    const int i  = gi0 + a * 15 + b;
                    const int s  = b % 3;
                    const int rb = b % 5;
                    const float4 hn = hfrom8(Lp[s], Bp[s], Rp[s]);
                    loadrow8(xp, i + 5, cb, Lp[s], Bp[s], Rp[s]);
                    h[(rb + 4) % 5] = hn;
                    const float4 S = f4add(acc, hn);

                    float4 o;
                    if (i >= BW + 2 && i < Hh - BW - 2) {
                        o = f4scale(S, 0.04f);
                    } else {
                        float4 NB = make_float4(0.f, 0.f, 0.f, 0.f);
                        #pragma unroll
                        for (int k = 0; k < 5; ++k) {
                            const int rk = i - 2 + k;        // OOB rows: h == 0
                            if (rk < BW || rk >= Hh - BW)
                                NB = f4add(NB, h[(rb + k) % 5]);
                        }
                        const int r0 = max(i - 2, 0), r1 = min(i + 2, Hh - 1);
                        const int nrows = r1 - r0 + 1;
                        const int nbr = max(0, min(r1, BW - 1) - r0 + 1)
                                      + max(0, r1 - max(r0, Hh - BW) + 1);
                        if (i < BW || i >= Hh - BW)
                            o = f4scale(NB, 1.0f / (float)(5 * nbr));
                        else
                            o = f4scale(f4sub(S, NB),
                                        1.0f / (float)(5 * (nrows - nbr)));
                    }
                    stcs4(os, o);
                    os += Ww;
                    acc = f4sub(S, h[rb]);
                }
            }
        }
    } else {
        // ========== frame columns 0..11 and 1428..1439 (naive) ==========
        for (int idx = tid; idx < 6 * RSTRIP; idx += 128) {
            const int q  = idx % 6;
            const int i  = gi0 + idx / 6;
            const int gq = (q < 3) ? q : (q + 354);          // {0,1,2,357,358,359}
            const int cb = 4 * gq - 4;
            const bool Aok = (cb >= 0);
            const bool Cok = (cb + 11 < Ww);

            float m[8];
            #pragma unroll
            for (int c = 0; c < 8; ++c) {
                const int col = cb + 2 + c;
                m[c] = (col < BW || col >= Ww - BW) ? 1.0f : 0.0f;
            }

            float4 S  = make_float4(0.f, 0.f, 0.f, 0.f);
            float4 NB = make_float4(0.f, 0.f, 0.f, 0.f);
            #pragma unroll
            for (int k = 0; k < 5; ++k) {
                const int r = i - 2 + k;
                if ((unsigned)r < (unsigned)Hh) {
                    const float* rowp = xp + (size_t)r * Ww;
                    const float4 Af = Aok ? *(const float4*)(rowp + cb)
                                          : make_float4(0.f, 0.f, 0.f, 0.f);
                    const float4 Bf = *(const float4*)(rowp + cb + 4);
                    const float4 Cf = Cok ? *(const float4*)(rowp + cb + 8)
                                          : make_float4(0.f, 0.f, 0.f, 0.f);
                    float4 h;
                    h.x = ((Af.z + Af.w) + (Bf.x + Bf.y)) + Bf.z;
                    h.y = h.x - Af.z + Bf.w;
                    h.z = h.y - Af.w + Cf.x;
                    h.w = h.z - Bf.x + Cf.y;
                    S = f4add(S, h);
                    if (r < BW || r >= Hh - BW) {
                        NB = f4add(NB, h);
                    } else {
                        const float w0 = Af.z * m[0], w1 = Af.w * m[1];
                        const float w2 = Bf.x * m[2], w3 = Bf.y * m[3];
                        const float w4 = Bf.z * m[4], w5 = Bf.w * m[5];
                        const float w6 = Cf.x * m[6], w7 = Cf.y * m[7];
                        float4 hb;
                        hb.x = ((w0 + w1) + (w2 + w3)) + w4;
                        hb.y = hb.x - w0 + w5;
                        hb.z = hb.y - w1 + w6;
                        hb.w = hb.z - w2 + w7;
                        NB = f4add(NB, hb);
                    }
                }
            }
            const int r0 = max(i - 2, 0), r1 = min(i + 2, Hh - 1);
            const int nrows = r1 - r0 + 1;
            const int nbr = max(0, min(r1, BW - 1) - r0 + 1)
                          + max(0, r1 - max(r0, Hh - BW) + 1);
            const bool rowBi = (i < BW || i >= Hh - BW);
            const float sv[4]  = {S.x, S.y, S.z, S.w};
            const float nbv[4] = {NB.x, NB.y, NB.z, NB.w};
            float ov[4];
            #pragma unroll
            for (int c = 0; c < 4; ++c) {
                const int j  = cb + 4 + c;
                const int c0 = max(j - 2, 0), c1 = min(j + 2, Ww - 1);
                const int ncols = c1 - c0 + 1;
                const int nbc = max(0, min(c1, BW - 1) - c0 + 1)
                              + max(0, c1 - max(c0, Ww - BW) + 1);
                const int  cntB = nbr * ncols + (nrows - nbr) * nbc;
                const bool mb   = rowBi || (j < BW || j >= Ww - BW);
                const float num = mb ? nbv[c] : (sv[c] - nbv[c]);
                const int   cnt = mb ? cntB : (nrows * ncols - cntB);
                ov[c] = num / (float)cnt;
            }
            stcs4(op + (size_t)i * Ww + (cb + 4),
                  make_float4(ov[0], ov[1], ov[2], ov[3]));
        }
    }
}

extern "C" void kernel_launch(void* const* d_in, const int* in_sizes, int n_in,
                              void* d_out, int out_size)
{
    const float* x = (const float*)d_in[0];
    float* out = (float*)d_out;
    const int planes = out_size / (Hh * Ww);     // 64
    dim3 grid(4, Hh / RSTRIP, planes);           // 4 x 16 x 64 = 4096 blocks
    seg_smooth<<<grid, 128>>>(x, out);
}